// round 15
// baseline (speedup 1.0000x reference)
#include <cuda_runtime.h>
#include <cstdint>
#include <cstddef>

// Problem constants
#define BB   256
#define KK   16
#define HH   512
#define DD   64

// Pass-1 tiling (R5 proven config)
#define BT       16     // b per block
#define HSPLIT   8      // h splits (grid.y)
#define HRANGE   64     // h per block
#define HC       2      // h per smem chunk
#define NCHUNK   32     // HRANGE / HC
#define STAGES   4
#define NTHREADS 384    // 12 warps: 2 b-groups x 3 matrices x 2 k-halves

// smem chunk: 64 rows (16 x-rows + 48 V-rows) x (HC*64) floats = 8192 floats = 32KB
#define CHUNK_FLOATS 8192
#define CHUNK_BYTES  32768
#define ROW_BYTES    512            // HC*DD*4 bytes per row per chunk
#define ROW_ULL      64             // HC*32 ull per row

typedef unsigned long long ull;

// scratch[hs][b][mat][k][d]  (fp32 partial sums over h-splits) : 25 MB
__device__ __align__(16) float g_scratch[(size_t)HSPLIT * BB * 3 * KK * DD];
// reduced logits (bias included), PERMUTED: [mat][k][b][d] : 3 MB
__device__ __align__(16) float g_red[(size_t)3 * KK * BB * DD];

#define RED_ELEMS4 (BB * 3 * KK * DD / 4)   // 196608 float4 outputs

// ---------------- PTX helpers ----------------
__device__ __forceinline__ void cp_async16(uint32_t dst, const void* src) {
    asm volatile("cp.async.ca.shared.global [%0], [%1], 16;\n" ::"r"(dst), "l"(src) : "memory");
}
__device__ __forceinline__ void cp_commit() {
    asm volatile("cp.async.commit_group;\n" ::: "memory");
}
template <int N>
__device__ __forceinline__ void cp_wait() {
    asm volatile("cp.async.wait_group %0;\n" ::"n"(N) : "memory");
}
// packed f32x2 FMA (Blackwell doubled-FP32 path; only reachable via PTX)
__device__ __forceinline__ void fma2(ull& d, ull a, ull b) {
    asm("fma.rn.f32x2 %0, %1, %2, %0;" : "+l"(d) : "l"(a), "l"(b));
}

// ---------------- Pass 1: 3x einsum bhd,khd->bkd (partial over h-split) ----------------
// smem chunk layout: [row 0..63][hh 0..1][d 0..63] floats
//   rows 0..15  = x[bBase+row], rows 16..63 = V{mat}[k]
// Per chunk: 2048 float4; thread covers rows r0+12i (r0=tid>>5), col=tid&31.
__device__ __forceinline__ void issue_chunk(
    uint32_t sbase, const char* const* rowPtr, int c, int r0, int colB)
{
    const uint32_t dstB = sbase + (uint32_t)(c & (STAGES - 1)) * CHUNK_BYTES + (uint32_t)colB;
    const size_t so = (size_t)c * ROW_BYTES + (size_t)colB;
#pragma unroll
    for (int i = 0; i < 6; i++) {
        const int row = r0 + 12 * i;
        if (i < 5 || r0 < 4) {                  // 4x32 threads do 6 rows, 8x32 do 5
            cp_async16(dstB + (uint32_t)row * 512u, rowPtr[row] + so);
        }
    }
    cp_commit();
}

__global__ void __launch_bounds__(NTHREADS, 1) k_gemm(
    const float* __restrict__ x, const float* __restrict__ Va,
    const float* __restrict__ Vm, const float* __restrict__ Vs)
{
    extern __shared__ float sm[];
    __shared__ const char* rowPtr[64];
    const uint32_t sbase = (uint32_t)__cvta_generic_to_shared(sm);

    const int tid = threadIdx.x;
    const int w = tid >> 5;
    const int l = tid & 31;           // lane -> d-pair (d = 2l, 2l+1)
    const int bg  = w / 6;            // b-group 0..1 (8 b each)
    const int rem = w - bg * 6;
    const int mat = rem >> 1;         // 0=alpha 1=mu 2=sigma
    const int kh  = rem & 1;          // k-half 0..1 (8 k each)
    const int bBase = blockIdx.x * BT;
    const int h0Base = blockIdx.y * HRANGE;

    // Build per-CTA row pointer table (base of each smem row's gmem source at h0Base)
    if (tid < 64) {
        const int row = tid;
        const float* p;
        if (row < BT) {
            p = x + (size_t)(bBase + row) * (HH * DD) + (size_t)h0Base * DD;
        } else {
            const int r = row - BT;
            const int m = r >> 4;
            const int k = r & 15;
            const float* Vp = (m == 0) ? Va : ((m == 1) ? Vm : Vs);
            p = Vp + (size_t)k * (HH * DD) + (size_t)h0Base * DD;
        }
        rowPtr[row] = (const char*)p;
    }
    __syncthreads();

    const int r0   = tid >> 5;        // 0..11 (copy row group)
    const int colB = (tid & 31) * 16; // byte offset within row slab

    const int xrow0 = bg * 8;
    const int vrow0 = 16 + mat * 16 + kh * 8;

    ull acc[8][8];                    // [rb][kt] f32x2 accumulators (128 regs)
#pragma unroll
    for (int r = 0; r < 8; r++)
#pragma unroll
        for (int k = 0; k < 8; k++) acc[r][k] = 0ull;

    issue_chunk(sbase, rowPtr, 0, r0, colB);
    issue_chunk(sbase, rowPtr, 1, r0, colB);

#pragma unroll 1
    for (int c = 0; c < NCHUNK; c++) {
        if (c + 2 < NCHUNK) {
            issue_chunk(sbase, rowPtr, c + 2, r0, colB);
            cp_wait<2>();                        // chunk c landed (c+1, c+2 in flight)
        } else if (c + 1 < NCHUNK) {
            cp_wait<1>();
        } else {
            cp_wait<0>();
        }
        __syncthreads();                         // single barrier per chunk

        const ull* buf = (const ull*)sm + (size_t)(c & (STAGES - 1)) * (CHUNK_FLOATS / 2);

#pragma unroll
        for (int hh = 0; hh < HC; hh++) {
            ull vv[8];
#pragma unroll
            for (int k = 0; k < 8; k++)
                vv[k] = buf[(vrow0 + k) * ROW_ULL + hh * 32 + l];
#pragma unroll
            for (int r = 0; r < 8; r++) {
                const ull xv = buf[(xrow0 + r) * ROW_ULL + hh * 32 + l];
#pragma unroll
                for (int k = 0; k < 8; k++) fma2(acc[r][k], xv, vv[k]);
            }
        }
    }

    // store partials: scratch[hs][b][mat][k][d]
    ull* sc = (ull*)g_scratch;
    const int hs = blockIdx.y;
#pragma unroll
    for (int r = 0; r < 8; r++) {
        const int b = bBase + bg * 8 + r;
        const size_t base = ((((size_t)hs * BB + b) * 3 + mat) * KK + kh * 8) * 32;
#pragma unroll
        for (int k = 0; k < 8; k++)
            sc[base + (size_t)k * 32 + l] = acc[r][k];
    }
}

// ------- Pass 1.5: reduce over h-splits (+ bias), permute -> g_red[mat][k][b][d] -------
__global__ void __launch_bounds__(256) k_reduce(
    const float* __restrict__ ba, const float* __restrict__ bm, const float* __restrict__ bs)
{
    const int idx = blockIdx.x * 256 + threadIdx.x;   // float4 index into scratch-flat order
    const float4* __restrict__ src = (const float4*)g_scratch;

    // src flat layout: ((b*3 + mat)*16 + k)*16 + dq   (float4 units)
    const int dq  = idx & 15;
    const int k   = (idx >> 4) & 15;
    const int rem = idx >> 8;            // 0..767 = b*3 + mat
    const int mat = rem % 3;
    const int b   = rem / 3;
    const float* bp = (mat == 0) ? ba : ((mat == 1) ? bm : bs);
    float4 s = ((const float4*)bp)[k * 16 + dq];

#pragma unroll
    for (int hs = 0; hs < HSPLIT; hs++) {
        const float4 v = src[(size_t)hs * RED_ELEMS4 + idx];
        s.x += v.x; s.y += v.y; s.z += v.z; s.w += v.w;
    }
    // dst layout: ((mat*16 + k)*BB + b)*16 + dq   (float4 units) — dq fastest => coalesced
    ((float4*)g_red)[(((size_t)mat * KK + k) * BB + b) * 16 + dq] = s;
}

// ---------------- Pass 2: softmax/logsumexp epilogue, sum over d ----------------
// One block per b (64 threads, thread = d). All loads warp-coalesced 128B rows.
__global__ void __launch_bounds__(64) k_final(
    const float* __restrict__ iv, float* __restrict__ out)
{
    __shared__ float sred[2];
    const int d = threadIdx.x;        // 0..63
    const int b = blockIdx.x;

    float ea[16], mu[16], ls[16];
    const float* __restrict__ rd = g_red;
    const size_t bd = (size_t)b * DD + d;
#pragma unroll
    for (int k = 0; k < 16; k++) ea[k] = rd[(size_t)(0 * KK + k) * (BB * DD) + bd];
#pragma unroll
    for (int k = 0; k < 16; k++) mu[k] = rd[(size_t)(1 * KK + k) * (BB * DD) + bd];
#pragma unroll
    for (int k = 0; k < 16; k++) ls[k] = rd[(size_t)(2 * KK + k) * (BB * DD) + bd];

    const float yv = iv[b * DD + d];

    const float HL2PI = 0.91893853320467274178f;
    float mA = -3.0e38f;
#pragma unroll
    for (int k = 0; k < 16; k++) mA = fmaxf(mA, ea[k]);
    float sA = 0.f;
#pragma unroll
    for (int k = 0; k < 16; k++) sA += __expf(ea[k] - mA);
    const float lseA = mA + __logf(sA);

    float t[16];
    float mT = -3.0e38f;
#pragma unroll
    for (int k = 0; k < 16; k++) {
        float s = fminf(fmaxf(ls[k], -20.f), 20.f);   // clip log_sigma
        const float z = (yv - mu[k]) * __expf(-s);
        const float tt = -0.5f * z * z + ea[k] - s;
        t[k] = tt;
        mT = fmaxf(mT, tt);
    }
    float sP = 0.f;
#pragma unroll
    for (int k = 0; k < 16; k++) sP += __expf(t[k] - mT);
    float contrib = mT + __logf(sP) - lseA - HL2PI;

    // reduce over 64 d: warp shuffle + 2-slot smem
#pragma unroll
    for (int off = 16; off > 0; off >>= 1)
        contrib += __shfl_down_sync(0xffffffffu, contrib, off);
    if ((d & 31) == 0) sred[d >> 5] = contrib;
    __syncthreads();
    if (d == 0) out[b] = sred[0] + sred[1];
}

// ---------------- launch ----------------
extern "C" void kernel_launch(void* const* d_in, const int* in_sizes, int n_in,
                              void* d_out, int out_size)
{
    (void)in_sizes; (void)n_in; (void)out_size;
    const float* x  = (const float*)d_in[0];
    const float* iv = (const float*)d_in[1];
    const float* Va = (const float*)d_in[2];
    const float* Vm = (const float*)d_in[3];
    const float* Vs = (const float*)d_in[4];
    const float* ba = (const float*)d_in[5];
    const float* bm = (const float*)d_in[6];
    const float* bs = (const float*)d_in[7];

    const int smemBytes = STAGES * CHUNK_BYTES;  // 128 KB, 4-stage ring
    cudaFuncSetAttribute(k_gemm, cudaFuncAttributeMaxDynamicSharedMemorySize, smemBytes);

    k_gemm<<<dim3(BB / BT, HSPLIT), NTHREADS, smemBytes>>>(x, Va, Vm, Vs);
    k_reduce<<<RED_ELEMS4 / 256, 256>>>(ba, bm, bs);
    k_final<<<BB, 64>>>(iv, (float*)d_out);
}

// round 16
// speedup vs baseline: 1.0007x; 1.0007x over previous
#include <cuda_runtime.h>
#include <cstdint>
#include <cstddef>

// Problem constants
#define BB   256
#define KK   16
#define HH   512
#define DD   64

// Pass-1 tiling (R5 proven config)
#define BT       16     // b per block
#define HSPLIT   8      // h splits (grid.y)
#define HRANGE   64     // h per block
#define HC       2      // h per smem chunk
#define NCHUNK   32     // HRANGE / HC
#define STAGES   4
#define NTHREADS 384    // 12 warps: 2 b-groups x 3 matrices x 2 k-halves

// smem chunk: 64 rows (16 x-rows + 48 V-rows) x (HC*64) floats = 8192 floats = 32KB
#define CHUNK_FLOATS 8192
#define CHUNK_BYTES  32768
#define ROW_BYTES    512            // HC*DD*4 bytes per row per chunk
#define ROW_ULL      64             // HC*32 ull per row

typedef unsigned long long ull;

// scratch[hs][b][mat][k][d]  (fp32 partial sums over h-splits) : 25 MB
__device__ __align__(16) float g_scratch[(size_t)HSPLIT * BB * 3 * KK * DD];
// reduced logits (bias included): [b][mat][k][d] : 3 MB
__device__ __align__(16) float g_red[(size_t)BB * 3 * KK * DD];

#define RED_ELEMS4 (BB * 3 * KK * DD / 4)   // 196608 float4 outputs

// ---------------- PTX helpers ----------------
__device__ __forceinline__ void cp_async16(uint32_t dst, const void* src) {
    asm volatile("cp.async.ca.shared.global [%0], [%1], 16;\n" ::"r"(dst), "l"(src) : "memory");
}
__device__ __forceinline__ void cp_commit() {
    asm volatile("cp.async.commit_group;\n" ::: "memory");
}
template <int N>
__device__ __forceinline__ void cp_wait() {
    asm volatile("cp.async.wait_group %0;\n" ::"n"(N) : "memory");
}
// packed f32x2 FMA (Blackwell doubled-FP32 path; only reachable via PTX)
__device__ __forceinline__ void fma2(ull& d, ull a, ull b) {
    asm("fma.rn.f32x2 %0, %1, %2, %0;" : "+l"(d) : "l"(a), "l"(b));
}

// ---------------- Pass 1: 3x einsum bhd,khd->bkd (partial over h-split) ----------------
// smem chunk layout: [row 0..63][hh 0..1][d 0..63] floats
//   rows 0..15  = x[bBase+row], rows 16..63 = V{mat}[k]
// Per chunk: 2048 float4; thread covers rows r0+12i (r0=tid>>5), col=tid&31.
__device__ __forceinline__ void issue_chunk(
    uint32_t sbase, const char* const* rowPtr, int c, int r0, int colB)
{
    const uint32_t dstB = sbase + (uint32_t)(c & (STAGES - 1)) * CHUNK_BYTES + (uint32_t)colB;
    const size_t so = (size_t)c * ROW_BYTES + (size_t)colB;
#pragma unroll
    for (int i = 0; i < 6; i++) {
        const int row = r0 + 12 * i;
        if (i < 5 || r0 < 4) {                  // 4x32 threads do 6 rows, 8x32 do 5
            cp_async16(dstB + (uint32_t)row * 512u, rowPtr[row] + so);
        }
    }
    cp_commit();
}

__global__ void __launch_bounds__(NTHREADS, 1) k_gemm(
    const float* __restrict__ x, const float* __restrict__ Va,
    const float* __restrict__ Vm, const float* __restrict__ Vs)
{
    extern __shared__ float sm[];
    __shared__ const char* rowPtr[64];
    const uint32_t sbase = (uint32_t)__cvta_generic_to_shared(sm);

    const int tid = threadIdx.x;
    const int w = tid >> 5;
    const int l = tid & 31;           // lane -> d-pair (d = 2l, 2l+1)
    const int bg  = w / 6;            // b-group 0..1 (8 b each)
    const int rem = w - bg * 6;
    const int mat = rem >> 1;         // 0=alpha 1=mu 2=sigma
    const int kh  = rem & 1;          // k-half 0..1 (8 k each)
    const int bBase = blockIdx.x * BT;
    const int h0Base = blockIdx.y * HRANGE;

    // Build per-CTA row pointer table (base of each smem row's gmem source at h0Base)
    if (tid < 64) {
        const int row = tid;
        const float* p;
        if (row < BT) {
            p = x + (size_t)(bBase + row) * (HH * DD) + (size_t)h0Base * DD;
        } else {
            const int r = row - BT;
            const int m = r >> 4;
            const int k = r & 15;
            const float* Vp = (m == 0) ? Va : ((m == 1) ? Vm : Vs);
            p = Vp + (size_t)k * (HH * DD) + (size_t)h0Base * DD;
        }
        rowPtr[row] = (const char*)p;
    }
    __syncthreads();

    const int r0   = tid >> 5;        // 0..11 (copy row group)
    const int colB = (tid & 31) * 16; // byte offset within row slab

    const int xrow0 = bg * 8;
    const int vrow0 = 16 + mat * 16 + kh * 8;

    ull acc[8][8];                    // [rb][kt] f32x2 accumulators (128 regs)
#pragma unroll
    for (int r = 0; r < 8; r++)
#pragma unroll
        for (int k = 0; k < 8; k++) acc[r][k] = 0ull;

    issue_chunk(sbase, rowPtr, 0, r0, colB);
    issue_chunk(sbase, rowPtr, 1, r0, colB);

#pragma unroll 1
    for (int c = 0; c < NCHUNK; c++) {
        if (c + 2 < NCHUNK) {
            issue_chunk(sbase, rowPtr, c + 2, r0, colB);
            cp_wait<2>();                        // chunk c landed (c+1, c+2 in flight)
        } else if (c + 1 < NCHUNK) {
            cp_wait<1>();
        } else {
            cp_wait<0>();
        }
        __syncthreads();                         // single barrier per chunk

        const ull* buf = (const ull*)sm + (size_t)(c & (STAGES - 1)) * (CHUNK_FLOATS / 2);

#pragma unroll
        for (int hh = 0; hh < HC; hh++) {
            ull vv[8];
#pragma unroll
            for (int k = 0; k < 8; k++)
                vv[k] = buf[(vrow0 + k) * ROW_ULL + hh * 32 + l];
#pragma unroll
            for (int r = 0; r < 8; r++) {
                const ull xv = buf[(xrow0 + r) * ROW_ULL + hh * 32 + l];
#pragma unroll
                for (int k = 0; k < 8; k++) fma2(acc[r][k], xv, vv[k]);
            }
        }
    }

    // store partials: scratch[hs][b][mat][k][d]
    ull* sc = (ull*)g_scratch;
    const int hs = blockIdx.y;
#pragma unroll
    for (int r = 0; r < 8; r++) {
        const int b = bBase + bg * 8 + r;
        const size_t base = ((((size_t)hs * BB + b) * 3 + mat) * KK + kh * 8) * 32;
#pragma unroll
        for (int k = 0; k < 8; k++)
            sc[base + (size_t)k * 32 + l] = acc[r][k];
    }
}

// ---------------- Pass 1.5: reduce over h-splits (+ bias), linear layout (R14) ----------
__global__ void __launch_bounds__(256) k_reduce(
    const float* __restrict__ ba, const float* __restrict__ bm, const float* __restrict__ bs)
{
    const int idx = blockIdx.x * 256 + threadIdx.x;   // float4 index into g_red
    const float4* __restrict__ src = (const float4*)g_scratch;

    // flat layout: ((b*3 + mat)*16 + k)*16 + dq   (in float4 units)
    const int dq  = idx & 15;
    const int k   = (idx >> 4) & 15;
    const int mat = (idx >> 8) % 3;
    const float* bp = (mat == 0) ? ba : ((mat == 1) ? bm : bs);
    float4 s = ((const float4*)bp)[k * 16 + dq];

#pragma unroll
    for (int hs = 0; hs < HSPLIT; hs++) {
        const float4 v = src[(size_t)hs * RED_ELEMS4 + idx];
        s.x += v.x; s.y += v.y; s.z += v.z; s.w += v.w;
    }
    ((float4*)g_red)[idx] = s;
}

// ---------------- Pass 2: softmax/logsumexp epilogue, sum over d (R14) ----------------
__global__ void __launch_bounds__(128) k_final(
    const float* __restrict__ iv, float* __restrict__ out)
{
    const int tx = threadIdx.x;                    // lane -> d-pair
    const int b = blockIdx.x * 4 + threadIdx.y;    // one warp per b

    float2 ea[16], mu[16], ls[16];

    const float2* __restrict__ rd = (const float2*)g_red;
    const size_t base = ((size_t)b * 3) * 512 + tx;  // float2 units; mat stride 512, k stride 32
#pragma unroll
    for (int k = 0; k < 16; k++) ea[k] = rd[base + (size_t)k * 32];
#pragma unroll
    for (int k = 0; k < 16; k++) mu[k] = rd[base + 512 + (size_t)k * 32];
#pragma unroll
    for (int k = 0; k < 16; k++) ls[k] = rd[base + 1024 + (size_t)k * 32];

    const float2 y2 = ((const float2*)iv)[b * 32 + tx];

    float contrib = 0.f;
    const float HL2PI = 0.91893853320467274178f;
#pragma unroll
    for (int comp = 0; comp < 2; comp++) {
        const float yv = comp ? y2.y : y2.x;
        float mA = -3.0e38f;
#pragma unroll
        for (int k = 0; k < 16; k++) {
            const float e = comp ? ea[k].y : ea[k].x;
            mA = fmaxf(mA, e);
        }
        float sA = 0.f;
#pragma unroll
        for (int k = 0; k < 16; k++) {
            const float e = comp ? ea[k].y : ea[k].x;
            sA += __expf(e - mA);
        }
        const float lseA = mA + __logf(sA);

        float t[16];
        float mT = -3.0e38f;
#pragma unroll
        for (int k = 0; k < 16; k++) {
            const float e = comp ? ea[k].y : ea[k].x;
            const float m = comp ? mu[k].y : mu[k].x;
            float s = comp ? ls[k].y : ls[k].x;
            s = fminf(fmaxf(s, -20.f), 20.f);       // clip log_sigma
            const float z = (yv - m) * __expf(-s);
            const float tt = -0.5f * z * z + e - s;
            t[k] = tt;
            mT = fmaxf(mT, tt);
        }
        float sP = 0.f;
#pragma unroll
        for (int k = 0; k < 16; k++) sP += __expf(t[k] - mT);
        contrib += mT + __logf(sP) - lseA - HL2PI;
    }

    // warp reduction over d (32 lanes x 2 d each = 64 d)
#pragma unroll
    for (int off = 16; off > 0; off >>= 1)
        contrib += __shfl_down_sync(0xffffffffu, contrib, off);
    if (tx == 0) out[b] = contrib;
}

// ---------------- launch ----------------
extern "C" void kernel_launch(void* const* d_in, const int* in_sizes, int n_in,
                              void* d_out, int out_size)
{
    (void)in_sizes; (void)n_in; (void)out_size;
    const float* x  = (const float*)d_in[0];
    const float* iv = (const float*)d_in[1];
    const float* Va = (const float*)d_in[2];
    const float* Vm = (const float*)d_in[3];
    const float* Vs = (const float*)d_in[4];
    const float* ba = (const float*)d_in[5];
    const float* bm = (const float*)d_in[6];
    const float* bs = (const float*)d_in[7];

    const int smemBytes = STAGES * CHUNK_BYTES;  // 128 KB, 4-stage ring
    cudaFuncSetAttribute(k_gemm, cudaFuncAttributeMaxDynamicSharedMemorySize, smemBytes);

    k_gemm<<<dim3(BB / BT, HSPLIT), NTHREADS, smemBytes>>>(x, Va, Vm, Vs);
    k_reduce<<<RED_ELEMS4 / 256, 256>>>(ba, bm, bs);
    k_final<<<BB / 4, dim3(32, 4)>>>(iv, (float*)d_out);
}

// round 17
// speedup vs baseline: 1.0461x; 1.0454x over previous
#include <cuda_runtime.h>
#include <cstdint>
#include <cstddef>

// Problem constants
#define BB   256
#define KK   16
#define HH   512
#define DD   64

// Pass-1 tiling (R5 proven config)
#define BT       16     // b per block
#define HSPLIT   8      // h splits (grid.y)
#define HRANGE   64     // h per block
#define HC       2      // h per smem chunk
#define NCHUNK   32     // HRANGE / HC
#define STAGES   4
#define NTHREADS 384    // 12 warps: 2 b-groups x 3 matrices x 2 k-halves

// smem chunk: 64 rows (16 x-rows + 48 V-rows) x (HC*64) floats = 8192 floats = 32KB
#define CHUNK_FLOATS 8192
#define CHUNK_BYTES  32768
#define ROW_BYTES    512            // HC*DD*4 bytes per row per chunk
#define ROW_ULL      64             // HC*32 ull per row

typedef unsigned long long ull;

// scratch[hs][b][mat][k][d]  (fp32 partial sums over h-splits) : 25 MB
__device__ __align__(16) float g_scratch[(size_t)HSPLIT * BB * 3 * KK * DD];

#define BLK_F4 768                  // float4 per (hs,b) slab: 3*16*16

// ---------------- PTX helpers ----------------
__device__ __forceinline__ void cp_async16(uint32_t dst, const void* src) {
    asm volatile("cp.async.ca.shared.global [%0], [%1], 16;\n" ::"r"(dst), "l"(src) : "memory");
}
__device__ __forceinline__ void cp_commit() {
    asm volatile("cp.async.commit_group;\n" ::: "memory");
}
template <int N>
__device__ __forceinline__ void cp_wait() {
    asm volatile("cp.async.wait_group %0;\n" ::"n"(N) : "memory");
}
// packed f32x2 FMA (Blackwell doubled-FP32 path; only reachable via PTX)
__device__ __forceinline__ void fma2(ull& d, ull a, ull b) {
    asm("fma.rn.f32x2 %0, %1, %2, %0;" : "+l"(d) : "l"(a), "l"(b));
}

// ---------------- Pass 1: 3x einsum bhd,khd->bkd (partial over h-split) ----------------
// smem chunk layout: [row 0..63][hh 0..1][d 0..63] floats
//   rows 0..15  = x[bBase+row], rows 16..63 = V{mat}[k]
// Per chunk: 2048 float4; thread covers rows r0+12i (r0=tid>>5), col=tid&31.
__device__ __forceinline__ void issue_chunk(
    uint32_t sbase, const char* const* rowPtr, int c, int r0, int colB)
{
    const uint32_t dstB = sbase + (uint32_t)(c & (STAGES - 1)) * CHUNK_BYTES + (uint32_t)colB;
    const size_t so = (size_t)c * ROW_BYTES + (size_t)colB;
#pragma unroll
    for (int i = 0; i < 6; i++) {
        const int row = r0 + 12 * i;
        if (i < 5 || r0 < 4) {                  // 4x32 threads do 6 rows, 8x32 do 5
            cp_async16(dstB + (uint32_t)row * 512u, rowPtr[row] + so);
        }
    }
    cp_commit();
}

__global__ void __launch_bounds__(NTHREADS, 1) k_gemm(
    const float* __restrict__ x, const float* __restrict__ Va,
    const float* __restrict__ Vm, const float* __restrict__ Vs)
{
    extern __shared__ float sm[];
    __shared__ const char* rowPtr[64];
    const uint32_t sbase = (uint32_t)__cvta_generic_to_shared(sm);

    const int tid = threadIdx.x;
    const int w = tid >> 5;
    const int l = tid & 31;           // lane -> d-pair (d = 2l, 2l+1)
    const int bg  = w / 6;            // b-group 0..1 (8 b each)
    const int rem = w - bg * 6;
    const int mat = rem >> 1;         // 0=alpha 1=mu 2=sigma
    const int kh  = rem & 1;          // k-half 0..1 (8 k each)
    const int bBase = blockIdx.x * BT;
    const int h0Base = blockIdx.y * HRANGE;

    // Build per-CTA row pointer table (base of each smem row's gmem source at h0Base)
    if (tid < 64) {
        const int row = tid;
        const float* p;
        if (row < BT) {
            p = x + (size_t)(bBase + row) * (HH * DD) + (size_t)h0Base * DD;
        } else {
            const int r = row - BT;
            const int m = r >> 4;
            const int k = r & 15;
            const float* Vp = (m == 0) ? Va : ((m == 1) ? Vm : Vs);
            p = Vp + (size_t)k * (HH * DD) + (size_t)h0Base * DD;
        }
        rowPtr[row] = (const char*)p;
    }
    __syncthreads();

    const int r0   = tid >> 5;        // 0..11 (copy row group)
    const int colB = (tid & 31) * 16; // byte offset within row slab

    const int xrow0 = bg * 8;
    const int vrow0 = 16 + mat * 16 + kh * 8;

    ull acc[8][8];                    // [rb][kt] f32x2 accumulators (128 regs)
#pragma unroll
    for (int r = 0; r < 8; r++)
#pragma unroll
        for (int k = 0; k < 8; k++) acc[r][k] = 0ull;

    issue_chunk(sbase, rowPtr, 0, r0, colB);
    issue_chunk(sbase, rowPtr, 1, r0, colB);

#pragma unroll 1
    for (int c = 0; c < NCHUNK; c++) {
        if (c + 2 < NCHUNK) {
            issue_chunk(sbase, rowPtr, c + 2, r0, colB);
            cp_wait<2>();                        // chunk c landed (c+1, c+2 in flight)
        } else if (c + 1 < NCHUNK) {
            cp_wait<1>();
        } else {
            cp_wait<0>();
        }
        __syncthreads();                         // single barrier per chunk

        const ull* buf = (const ull*)sm + (size_t)(c & (STAGES - 1)) * (CHUNK_FLOATS / 2);

#pragma unroll
        for (int hh = 0; hh < HC; hh++) {
            ull vv[8];
#pragma unroll
            for (int k = 0; k < 8; k++)
                vv[k] = buf[(vrow0 + k) * ROW_ULL + hh * 32 + l];
#pragma unroll
            for (int r = 0; r < 8; r++) {
                const ull xv = buf[(xrow0 + r) * ROW_ULL + hh * 32 + l];
#pragma unroll
                for (int k = 0; k < 8; k++) fma2(acc[r][k], xv, vv[k]);
            }
        }
    }

    // store partials: scratch[hs][b][mat][k][d]
    ull* sc = (ull*)g_scratch;
    const int hs = blockIdx.y;
#pragma unroll
    for (int r = 0; r < 8; r++) {
        const int b = bBase + bg * 8 + r;
        const size_t base = ((((size_t)hs * BB + b) * 3 + mat) * KK + kh * 8) * 32;
#pragma unroll
        for (int k = 0; k < 8; k++)
            sc[base + (size_t)k * 32 + l] = acc[r][k];
    }
}

// ---------------- Fused epilogue: hs-reduce + bias + softmax/logsumexp + d-sum ----------
// One block per b, 256 threads. Thread t = (k = t>>4, dq = t&15).
__global__ void __launch_bounds__(256) k_epi(
    const float* __restrict__ iv,
    const float* __restrict__ ba, const float* __restrict__ bm, const float* __restrict__ bs,
    float* __restrict__ out)
{
    __shared__ float s_ea[KK][DD + 4];
    __shared__ float s_mu[KK][DD + 4];
    __shared__ float s_ls[KK][DD + 4];
    __shared__ float sred[2];

    const int t = threadIdx.x;
    const int b = blockIdx.x;
    const int k = t >> 4;             // 0..15
    const int dq = t & 15;            // float4 group of d

    // bias init
    float4 ea = ((const float4*)ba)[k * 16 + dq];
    float4 mu = ((const float4*)bm)[k * 16 + dq];
    float4 ls = ((const float4*)bs)[k * 16 + dq];

    // accumulate 8 h-split partials straight from scratch (L2-hot)
    const float4* __restrict__ src = (const float4*)g_scratch;
#pragma unroll
    for (int hs = 0; hs < HSPLIT; hs++) {
        const float4* p = src + ((size_t)hs * BB + b) * BLK_F4 + t;
        const float4 va = p[0];       // mat 0 (alpha)
        const float4 vm = p[256];     // mat 1 (mu)
        const float4 vs = p[512];     // mat 2 (sigma)
        ea.x += va.x; ea.y += va.y; ea.z += va.z; ea.w += va.w;
        mu.x += vm.x; mu.y += vm.y; mu.z += vm.z; mu.w += vm.w;
        ls.x += vs.x; ls.y += vs.y; ls.z += vs.z; ls.w += vs.w;
    }

    // transpose to [k][d] via smem
    s_ea[k][4 * dq + 0] = ea.x; s_ea[k][4 * dq + 1] = ea.y;
    s_ea[k][4 * dq + 2] = ea.z; s_ea[k][4 * dq + 3] = ea.w;
    s_mu[k][4 * dq + 0] = mu.x; s_mu[k][4 * dq + 1] = mu.y;
    s_mu[k][4 * dq + 2] = mu.z; s_mu[k][4 * dq + 3] = mu.w;
    s_ls[k][4 * dq + 0] = ls.x; s_ls[k][4 * dq + 1] = ls.y;
    s_ls[k][4 * dq + 2] = ls.z; s_ls[k][4 * dq + 3] = ls.w;
    __syncthreads();

    float contrib = 0.f;
    if (t < DD) {
        const int d = t;
        const float yv = iv[b * DD + d];
        const float HL2PI = 0.91893853320467274178f;

        float eav[KK], muv[KK], lsv[KK];
#pragma unroll
        for (int kk = 0; kk < KK; kk++) {
            eav[kk] = s_ea[kk][d];
            muv[kk] = s_mu[kk][d];
            lsv[kk] = s_ls[kk][d];
        }

        float mA = -3.0e38f;
#pragma unroll
        for (int kk = 0; kk < KK; kk++) mA = fmaxf(mA, eav[kk]);
        float sA = 0.f;
#pragma unroll
        for (int kk = 0; kk < KK; kk++) sA += __expf(eav[kk] - mA);
        const float lseA = mA + __logf(sA);

        float tv[KK];
        float mT = -3.0e38f;
#pragma unroll
        for (int kk = 0; kk < KK; kk++) {
            float s = fminf(fmaxf(lsv[kk], -20.f), 20.f);   // clip log_sigma
            const float z = (yv - muv[kk]) * __expf(-s);
            const float tt = -0.5f * z * z + eav[kk] - s;
            tv[kk] = tt;
            mT = fmaxf(mT, tt);
        }
        float sP = 0.f;
#pragma unroll
        for (int kk = 0; kk < KK; kk++) sP += __expf(tv[kk] - mT);
        contrib = mT + __logf(sP) - lseA - HL2PI;
    }

    // reduce over d (warps 0 and 1 hold d = 0..63)
    if (t < DD) {
#pragma unroll
        for (int off = 16; off > 0; off >>= 1)
            contrib += __shfl_down_sync(0xffffffffu, contrib, off);
        if ((t & 31) == 0) sred[t >> 5] = contrib;
    }
    __syncthreads();
    if (t == 0) out[b] = sred[0] + sred[1];
}

// ---------------- launch ----------------
extern "C" void kernel_launch(void* const* d_in, const int* in_sizes, int n_in,
                              void* d_out, int out_size)
{
    (void)in_sizes; (void)n_in; (void)out_size;
    const float* x  = (const float*)d_in[0];
    const float* iv = (const float*)d_in[1];
    const float* Va = (const float*)d_in[2];
    const float* Vm = (const float*)d_in[3];
    const float* Vs = (const float*)d_in[4];
    const float* ba = (const float*)d_in[5];
    const float* bm = (const float*)d_in[6];
    const float* bs = (const float*)d_in[7];

    const int smemBytes = STAGES * CHUNK_BYTES;  // 128 KB, 4-stage ring
    cudaFuncSetAttribute(k_gemm, cudaFuncAttributeMaxDynamicSharedMemorySize, smemBytes);

    k_gemm<<<dim3(BB / BT, HSPLIT), NTHREADS, smemBytes>>>(x, Va, Vm, Vs);
    k_epi<<<BB, 256>>>(iv, ba, bm, bs, (float*)d_out);
}